// round 16
// baseline (speedup 1.0000x reference)
#include <cuda_runtime.h>
#include <cuda_fp16.h>

#define NN 50000
#define NE 800000
#define D  128
#define DE 64
#define CAP 80

typedef unsigned long long ull;

// ---------------- device scratch (no allocs allowed) ----------------
__device__ __align__(16) int   g_deg [NN];
__device__ __align__(16) int   g_cur [NN];         // build cursor (deg split out)
__device__ __align__(16) float g_norm[NN];
__device__ __align__(16) ull   g_g16 [NN * 32];    // fp16x4 per lane-slot: norm[n]*h[n]
__device__ __align__(16) float g_agge[NN * DE];    // sum_{e->n} norm[src]*efeat
__device__ __align__(16) float g_se  [NN];         // sum_{e->n} norm[src]
__device__ __align__(16) int   g_perm[NN * CAP];   // per-dst src list
__device__ __align__(16) int2  g_ovf [2048];       // overflow {src, dst}
__device__ int g_novf;

// ---------------- PTX helpers ----------------
__device__ __forceinline__ void fma2(ull &d, ull a, ull b) {
    asm("fma.rn.f32x2 %0, %1, %2, %0;" : "+l"(d) : "l"(a), "l"(b));
}
__device__ __forceinline__ ull dup2(float x) {
    ull r; asm("mov.b64 %0, {%1, %1};" : "=l"(r) : "f"(x)); return r;
}
__device__ __forceinline__ float2 unpk(ull v) {
    float2 r; asm("mov.b64 {%0, %1}, %2;" : "=f"(r.x), "=f"(r.y) : "l"(v)); return r;
}
__device__ __forceinline__ void red4(float* p, float4 v) {
    asm volatile("red.global.add.v4.f32 [%0], {%1, %2, %3, %4};"
                 :: "l"(p), "f"(v.x), "f"(v.y), "f"(v.z), "f"(v.w) : "memory");
}
__device__ __forceinline__ ull ldg1(const ull* p) {
    ull r; asm("ld.global.nc.u64 %0, [%1];" : "=l"(r) : "l"(p)); return r;
}
__device__ __forceinline__ float4 ldg4_ef(const float* p, ull pol) {
    float4 r;
    asm("ld.global.nc.L2::cache_hint.v4.f32 {%0, %1, %2, %3}, [%4], %5;"
        : "=f"(r.x), "=f"(r.y), "=f"(r.z), "=f"(r.w) : "l"(p), "l"(pol));
    return r;
}
__device__ __forceinline__ float ldgf(const float* p) {
    float r; asm("ld.global.nc.f32 %0, [%1];" : "=f"(r) : "l"(p)); return r;
}
__device__ __forceinline__ void acc_h4(float4 &acc, ull v) {
    unsigned lo = (unsigned)v, hi = (unsigned)(v >> 32);
    float2 f01 = __half22float2(*(__half2*)&lo);
    float2 f23 = __half22float2(*(__half2*)&hi);
    acc.x += f01.x; acc.y += f01.y; acc.z += f23.x; acc.w += f23.y;
}
__device__ __forceinline__ unsigned h2bits(float a, float b) {
    __half2 h = __floats2half2_rn(a, b);
    return *(unsigned*)&h;
}
__device__ __forceinline__ ull pack_h4u(float a, float b, float c, float d) {
    unsigned u0 = h2bits(a, b), u1 = h2bits(c, d);
    return ((ull)u1 << 32) | u0;
}
__device__ __forceinline__ unsigned smem_u32(const void* p) {
    unsigned a;
    asm("{ .reg .u64 t; cvta.to.shared.u64 t, %1; cvt.u32.u64 %0, t; }"
        : "=r"(a) : "l"(p));
    return a;
}
__device__ __forceinline__ void ldsm_x4(unsigned &r0, unsigned &r1,
                                        unsigned &r2, unsigned &r3, unsigned a) {
    asm volatile("ldmatrix.sync.aligned.m8n8.x4.shared.b16 {%0,%1,%2,%3}, [%4];"
                 : "=r"(r0), "=r"(r1), "=r"(r2), "=r"(r3) : "r"(a));
}
__device__ __forceinline__ void ldsm_x4t(unsigned &r0, unsigned &r1,
                                         unsigned &r2, unsigned &r3, unsigned a) {
    asm volatile("ldmatrix.sync.aligned.m8n8.x4.trans.shared.b16 {%0,%1,%2,%3}, [%4];"
                 : "=r"(r0), "=r"(r1), "=r"(r2), "=r"(r3) : "r"(a));
}
__device__ __forceinline__ void mma_f16(float c[4], unsigned a0, unsigned a1,
                                        unsigned a2, unsigned a3,
                                        unsigned b0, unsigned b1) {
    asm("mma.sync.aligned.m16n8k16.row.col.f32.f16.f16.f32 "
        "{%0,%1,%2,%3}, {%4,%5,%6,%7}, {%8,%9}, {%0,%1,%2,%3};"
        : "+f"(c[0]), "+f"(c[1]), "+f"(c[2]), "+f"(c[3])
        : "r"(a0), "r"(a1), "r"(a2), "r"(a3), "r"(b0), "r"(b1));
}

// ---------------- K0a: zero small state (deg, cur, se, novf) ----------------
__global__ void k_zero0() {
    int i = blockIdx.x * blockDim.x + threadIdx.x;
    int st = gridDim.x * blockDim.x;
    for (int j = i; j < NN; j += st) { g_deg[j] = 0; g_cur[j] = 0; g_se[j] = 0.f; }
    if (i == 0) g_novf = 0;
}

// ---------------- K0b: zero agge (before edge_e) ----------------
__global__ void k_zeroA() {
    int i = blockIdx.x * blockDim.x + threadIdx.x;
    int st = gridDim.x * blockDim.x;
    float4 z = make_float4(0.f, 0.f, 0.f, 0.f);
    for (int j = i; j < NN * DE / 4; j += st) ((float4*)g_agge)[j] = z;
}

// ---------------- K1a: in-degree only (unblocks norm -> node_mma fork) -------
__global__ void k_deg(const int* __restrict__ dst) {
    int e = blockIdx.x * blockDim.x + threadIdx.x;
    if (e < NE) atomicAdd(&g_deg[dst[e]], 1);
}

// ---------------- K1b: norm = (deg+1)^-1/2 ----------------
__global__ void k_norm() {
    int i = blockIdx.x * blockDim.x + threadIdx.x;
    if (i < NN) g_norm[i] = rsqrtf((float)g_deg[i] + 1.0f);
}

// ---------------- K1c: build per-dst src buckets (separate cursor) ----------
__global__ void k_build(const int* __restrict__ src, const int* __restrict__ dst) {
    int e = blockIdx.x * blockDim.x + threadIdx.x;
    if (e >= NE) return;
    int d = dst[e], s = src[e];
    int c = atomicAdd(&g_cur[d], 1);
    if (c < CAP) {
        g_perm[d * CAP + c] = s;
    } else {
        int o = atomicAdd(&g_novf, 1);
        if (o < 2048) g_ovf[o] = make_int2(s, d);
    }
}

// ---------------- KA: edge-parallel efeat scatter (2 edges per round) ----------------
__global__ __launch_bounds__(256) void k_edge_e(
    const int* __restrict__ src, const int* __restrict__ dst,
    const float* __restrict__ efeat)
{
    int lane = threadIdx.x & 31;
    int warp = (blockIdx.x * blockDim.x + threadIdx.x) >> 5;   // 25000 warps
    int e0   = warp * 32;
    if (e0 >= NE) return;

    int s = src[e0 + lane];
    int d = dst[e0 + lane];
    float ns = ldgf(&g_norm[s]);
    atomicAdd(&g_se[d], ns);

    ull pol;
    asm("createpolicy.fractional.L2::evict_first.b64 %0, 1.0;" : "=l"(pol));

    int half = lane >> 4;
    int l16  = lane & 15;
    const float* ep = &efeat[(size_t)e0 * DE + 4 * l16];

    #pragma unroll
    for (int j = 0; j < 32; j += 2) {
        int idx = j + half;
        int   dj  = __shfl_sync(0xffffffffu, d, idx);
        float nsj = __shfl_sync(0xffffffffu, ns, idx);
        float4 ev = ldg4_ef(ep + (size_t)idx * DE, pol);
        red4(&g_agge[(size_t)dj * DE + 4 * l16],
             make_float4(nsj * ev.x, nsj * ev.y, nsj * ev.z, nsj * ev.w));
    }
}

// ---------------- K2: fp16 HMMA node GEMM (ldmatrix-fed) --------------------------
__global__ __launch_bounds__(256, 2) void k_node_mma(
    const float* __restrict__ nfeat, const float* __restrict__ Wn,
    const float* __restrict__ bn, const float* __restrict__ resid,
    float* __restrict__ out)
{
    extern __shared__ __half smh[];
    __half* sA = smh;               // [128][136] fp16
    __half* sB = smh + 128 * 136;   // [128][136] fp16 (Wn as [k][n])

    int t = threadIdx.x, lane = t & 31, w = t >> 5;
    int g = lane >> 2, tig = lane & 3;
    int q = lane >> 3, l8 = lane & 7;

    // stage Wn once as fp16
    for (int i = t; i < 128 * 32; i += 256) {
        int k  = i >> 5;
        int c4 = (i & 31) * 4;
        float4 v = *(const float4*)&Wn[(size_t)k * 128 + c4];
        *(ull*)&sB[k * 136 + c4] = pack_h4u(v.x, v.y, v.z, v.w);
    }

    unsigned sAu = smem_u32(sA), sBu = smem_u32(sB);
    unsigned addrA0 = sAu + ((unsigned)((16 * w + (q & 1) * 8 + l8) * 136
                                        + (q >> 1) * 8) << 1);
    unsigned addrB0 = sBu + ((unsigned)(((q & 1) * 8 + l8) * 136
                                        + (q >> 1) * 8) << 1);

    const int NT = (NN + 127) / 128;   // 391
    for (int tile = blockIdx.x; tile < NT; tile += gridDim.x) {
        __syncthreads();
        for (int i = t; i < 128 * 32; i += 256) {
            int r  = i >> 5;
            int c4 = (i & 31) * 4;
            int gn = tile * 128 + r;
            float4 v = make_float4(0.f, 0.f, 0.f, 0.f);
            if (gn < NN) v = *(const float4*)&nfeat[(size_t)gn * 128 + c4];
            *(ull*)&sA[r * 136 + c4] = pack_h4u(v.x, v.y, v.z, v.w);
        }
        __syncthreads();

        float c[16][4];
        #pragma unroll
        for (int j = 0; j < 16; j++)
            c[j][0] = c[j][1] = c[j][2] = c[j][3] = 0.f;

        #pragma unroll
        for (int ks = 0; ks < 8; ks++) {
            int k0 = ks * 16;
            unsigned a0, a1, a2, a3;
            ldsm_x4(a0, a1, a2, a3, addrA0 + (k0 << 1));
            #pragma unroll
            for (int jp = 0; jp < 8; jp++) {
                unsigned b0, b1, b2, b3;
                ldsm_x4t(b0, b1, b2, b3,
                         addrB0 + ((unsigned)(k0 * 136 + 16 * jp) << 1));
                mma_f16(c[2 * jp],     a0, a1, a2, a3, b0, b1);
                mma_f16(c[2 * jp + 1], a0, a1, a2, a3, b2, b3);
            }
        }

        int n0 = tile * 128 + 16 * w + g;
        int n1 = n0 + 8;
        bool v0 = n0 < NN, v1 = n1 < NN;
        float dv0 = v0 ? (float)g_deg[n0] + 1.0f : 1.0f;
        float dv1 = v1 ? (float)g_deg[n1] + 1.0f : 1.0f;
        float inv0 = 1.0f / dv0, nr0 = rsqrtf(dv0);
        float inv1 = 1.0f / dv1, nr1 = rsqrtf(dv1);

        unsigned* g32 = (unsigned*)g_g16;
        #pragma unroll
        for (int j = 0; j < 16; j++) {
            int col = 8 * j + 2 * tig;
            float2 bn2 = *(const float2*)&bn[col];
            float2 r2  = *(const float2*)&resid[col];
            float h0 = c[j][0] + bn2.x, h1 = c[j][1] + bn2.y;
            float h2 = c[j][2] + bn2.x, h3 = c[j][3] + bn2.y;
            if (v0) {
                g32[(size_t)n0 * 64 + 4 * j + tig] = h2bits(nr0 * h0, nr0 * h1);
                *(float2*)&out[(size_t)n0 * D + col] =
                    make_float2((h0 + r2.x) * inv0, (h1 + r2.y) * inv0);
            }
            if (v1) {
                g32[(size_t)n1 * 64 + 4 * j + tig] = h2bits(nr1 * h2, nr1 * h3);
                *(float2*)&out[(size_t)n1 * D + col] =
                    make_float2((h2 + r2.x) * inv1, (h3 + r2.y) * inv1);
            }
        }
    }
}

// ---------------- K3: tiled GEMM  out += norm * (agge@We + se*be)  [red4] ----------
__global__ __launch_bounds__(256) void k_gemm2(
    const float* __restrict__ We, const float* __restrict__ be,
    float* __restrict__ out)
{
    extern __shared__ ull smg[];
    ull*   sWe = smg;                      // [64][64] u64 (We dim-pairs) = 32 KB
    float* sAg = (float*)(smg + 64 * 64);  // [k][node] = 16 KB

    int t = threadIdx.x, lane = t & 31, w = t >> 5;

    const ulonglong2* We128 = (const ulonglong2*)We;
    ulonglong2* sWe2 = (ulonglong2*)sWe;
    for (int i = t; i < 64 * 64 / 2; i += 256) sWe2[i] = We128[i];

    float4 be4 = *(const float4*)&be[4 * lane];

    int nodeL = t & 63;
    int q     = t >> 6;

    const int NT = (NN + 63) / 64;
    for (int tile = blockIdx.x; tile < NT; tile += gridDim.x) {
        __syncthreads();
        int gn = tile * 64 + nodeL;
        #pragma unroll
        for (int i = 0; i < 4; i++) {
            int k0 = 16 * q + 4 * i;
            float4 v = make_float4(0.f, 0.f, 0.f, 0.f);
            if (gn < NN) v = *(const float4*)&g_agge[(size_t)gn * DE + k0];
            sAg[(k0 + 0) * 64 + nodeL] = v.x;
            sAg[(k0 + 1) * 64 + nodeL] = v.y;
            sAg[(k0 + 2) * 64 + nodeL] = v.z;
            sAg[(k0 + 3) * 64 + nodeL] = v.w;
        }
        __syncthreads();

        ull acc[8][2];
        #pragma unroll
        for (int j = 0; j < 8; j++) { acc[j][0] = 0ULL; acc[j][1] = 0ULL; }

        #pragma unroll 8
        for (int k = 0; k < 64; k++) {
            ulonglong2 wv = *(const ulonglong2*)&sWe[k * 64 + 2 * lane];
            float4 f0 = *(const float4*)&sAg[k * 64 + 8 * w];
            float4 f1 = *(const float4*)&sAg[k * 64 + 8 * w + 4];
            float fv[8] = {f0.x, f0.y, f0.z, f0.w, f1.x, f1.y, f1.z, f1.w};
            #pragma unroll
            for (int j = 0; j < 8; j++) {
                ull dj = dup2(fv[j]);
                fma2(acc[j][0], dj, wv.x);
                fma2(acc[j][1], dj, wv.y);
            }
        }

        #pragma unroll
        for (int j = 0; j < 8; j++) {
            int n = tile * 64 + 8 * w + j;
            if (n >= NN) continue;
            float nr = g_norm[n];
            float se = g_se[n];
            float2 p0 = unpk(acc[j][0]), p1 = unpk(acc[j][1]);
            red4(&out[(size_t)n * D + 4 * lane],
                 make_float4(nr * (p0.x + se * be4.x), nr * (p0.y + se * be4.y),
                             nr * (p1.x + se * be4.z), nr * (p1.y + se * be4.w)));
        }
    }
}

// ---------------- K4: node-parallel fp16 g gather (no smem; red4 epilogue) -------------
__global__ __launch_bounds__(256) void k_gath(float* __restrict__ out)
{
    int t = threadIdx.x, lane = t & 31, w = t >> 5;
    int n = blockIdx.x * 8 + w;   // grid = 6250 * 8 warps = 50000
    if (n >= NN) return;

    int deg  = g_deg[n];
    int dcap = deg < CAP ? deg : CAP;
    int base = n * CAP;

    float4 acc = make_float4(0.f, 0.f, 0.f, 0.f);

    for (int c0 = 0; c0 < dcap; c0 += 32) {
        int m = dcap - c0; if (m > 32) m = 32;
        int s_l = 0;
        if (lane < m) s_l = g_perm[base + c0 + lane];

        int i = 0;
        for (; i + 8 <= m; i += 8) {
            int sa[8];
            #pragma unroll
            for (int k = 0; k < 8; k++) sa[k] = __shfl_sync(0xffffffffu, s_l, i + k);
            ull gv[8];
            #pragma unroll
            for (int k = 0; k < 8; k++) gv[k] = ldg1(&g_g16[(size_t)sa[k] * 32 + lane]);
            #pragma unroll
            for (int k = 0; k < 8; k++) acc_h4(acc, gv[k]);
        }
        for (; i < m; i++) {
            int s = __shfl_sync(0xffffffffu, s_l, i);
            ull gv = ldg1(&g_g16[(size_t)s * 32 + lane]);
            acc_h4(acc, gv);
        }
    }

    float nr = g_norm[n];
    red4(&out[(size_t)n * D + 4 * lane],
         make_float4(nr * acc.x, nr * acc.y, nr * acc.z, nr * acc.w));
}

// ---------------- K5: overflow fallback — add missing g contributions ----------------
__global__ void k_ovf(float* __restrict__ out) {
    int cnt = g_novf; if (cnt > 2048) cnt = 2048;
    if (cnt <= 0) return;
    int lane = threadIdx.x & 31;
    int warp = (blockIdx.x * blockDim.x + threadIdx.x) >> 5;
    int nw   = (gridDim.x * blockDim.x) >> 5;
    for (int o = warp; o < cnt; o += nw) {
        int2 v = g_ovf[o];
        int s = v.x, d = v.y;
        float nd = g_norm[d];
        float4 acc = make_float4(0.f, 0.f, 0.f, 0.f);
        acc_h4(acc, g_g16[(size_t)s * 32 + lane]);
        red4(&out[(size_t)d * D + 4 * lane],
             make_float4(nd * acc.x, nd * acc.y, nd * acc.z, nd * acc.w));
    }
}

// ---------------- launch: early fork — deg/norm unblock node_mma ASAP ----------------
extern "C" void kernel_launch(void* const* d_in, const int* in_sizes, int n_in,
                              void* d_out, int out_size)
{
    const int*   src   = (const int*)  d_in[0];
    const int*   dst   = (const int*)  d_in[1];
    const float* nfeat = (const float*)d_in[2];
    const float* efeat = (const float*)d_in[3];
    const float* Wn    = (const float*)d_in[4];
    const float* bn    = (const float*)d_in[5];
    const float* We    = (const float*)d_in[6];
    const float* be    = (const float*)d_in[7];
    const float* resid = (const float*)d_in[8];
    float* out = (float*)d_out;

    const int SM_MMA = 2 * 128 * 136 * 2;          // 69.6 KB (fp16 A + B)
    const int SM_G2  = 64 * 64 * 8 + 64 * 64 * 4;  // 48 KB
    cudaFuncSetAttribute(k_node_mma, cudaFuncAttributeMaxDynamicSharedMemorySize, SM_MMA);
    cudaFuncSetAttribute(k_gemm2,    cudaFuncAttributeMaxDynamicSharedMemorySize, SM_G2);

    cudaStream_t sA;
    cudaStreamCreateWithFlags(&sA, cudaStreamNonBlocking);
    cudaEvent_t eNorm, eBuild, eNode, eEnd;
    cudaEventCreateWithFlags(&eNorm,  cudaEventDisableTiming);
    cudaEventCreateWithFlags(&eBuild, cudaEventDisableTiming);
    cudaEventCreateWithFlags(&eNode,  cudaEventDisableTiming);
    cudaEventCreateWithFlags(&eEnd,   cudaEventDisableTiming);

    // s0: minimal chain to unblock the MMA fork
    k_zero0<<<196, 256>>>();
    k_deg  <<<(NE + 255) / 256, 256>>>(dst);
    k_norm <<<(NN + 255) / 256, 256>>>();
    cudaEventRecord(eNorm, 0);

    // sA: tensor-core GEMM as soon as deg/norm exist
    cudaStreamWaitEvent(sA, eNorm, 0);
    k_node_mma<<<296, 256, SM_MMA, sA>>>(nfeat, Wn, bn, resid, out);
    cudaEventRecord(eNode, sA);

    // s0 (concurrent with node_mma): agge zero, bucket build, efeat stream
    k_zeroA<<<912, 256>>>();
    k_build<<<(NE + 255) / 256, 256>>>(src, dst);
    cudaEventRecord(eBuild, 0);
    k_edge_e<<<3125, 256, 0, 0>>>(src, dst, efeat);

    // sA: gather chain (needs g_perm from build + g_g16/out from node_mma)
    cudaStreamWaitEvent(sA, eBuild, 0);
    k_gath<<<6250, 256, 0, sA>>>(out);
    k_ovf <<<16, 256, 0, sA>>>(out);

    // s0: gemm2 (after edge_e in s0 order; needs out base from node_mma)
    cudaStreamWaitEvent(0, eNode, 0);
    k_gemm2<<<782, 256, SM_G2, 0>>>(We, be, out);

    // join
    cudaEventRecord(eEnd, sA);
    cudaStreamWaitEvent(0, eEnd, 0);
}

// round 17
// speedup vs baseline: 1.0835x; 1.0835x over previous
#include <cuda_runtime.h>
#include <cuda_fp16.h>

#define NN 50000
#define NE 800000
#define D  128
#define DE 64
#define CAP 80

typedef unsigned long long ull;

// ---------------- device scratch (no allocs allowed) ----------------
__device__ __align__(16) int   g_deg [NN];
__device__ __align__(16) float g_norm[NN];
__device__ __align__(16) ull   g_g16 [NN * 32];    // fp16x4 per lane-slot: norm[n]*h[n]
__device__ __align__(16) float g_agge[NN * DE];    // sum_{e->n} norm[src]*efeat
__device__ __align__(16) float g_se  [NN];         // sum_{e->n} norm[src]
__device__ __align__(16) int   g_perm[NN * CAP];   // per-dst src list
__device__ __align__(16) int2  g_ovf [2048];       // overflow {src, dst}
__device__ int g_novf;

// ---------------- PTX helpers ----------------
__device__ __forceinline__ void fma2(ull &d, ull a, ull b) {
    asm("fma.rn.f32x2 %0, %1, %2, %0;" : "+l"(d) : "l"(a), "l"(b));
}
__device__ __forceinline__ ull dup2(float x) {
    ull r; asm("mov.b64 %0, {%1, %1};" : "=l"(r) : "f"(x)); return r;
}
__device__ __forceinline__ float2 unpk(ull v) {
    float2 r; asm("mov.b64 {%0, %1}, %2;" : "=f"(r.x), "=f"(r.y) : "l"(v)); return r;
}
__device__ __forceinline__ void red4(float* p, float4 v) {
    asm volatile("red.global.add.v4.f32 [%0], {%1, %2, %3, %4};"
                 :: "l"(p), "f"(v.x), "f"(v.y), "f"(v.z), "f"(v.w) : "memory");
}
__device__ __forceinline__ ull ldg1(const ull* p) {
    ull r; asm("ld.global.nc.u64 %0, [%1];" : "=l"(r) : "l"(p)); return r;
}
__device__ __forceinline__ float4 ldg4_ef(const float* p, ull pol) {
    float4 r;
    asm("ld.global.nc.L2::cache_hint.v4.f32 {%0, %1, %2, %3}, [%4], %5;"
        : "=f"(r.x), "=f"(r.y), "=f"(r.z), "=f"(r.w) : "l"(p), "l"(pol));
    return r;
}
__device__ __forceinline__ float ldgf(const float* p) {
    float r; asm("ld.global.nc.f32 %0, [%1];" : "=f"(r) : "l"(p)); return r;
}
__device__ __forceinline__ void acc_h4(float4 &acc, ull v) {
    unsigned lo = (unsigned)v, hi = (unsigned)(v >> 32);
    float2 f01 = __half22float2(*(__half2*)&lo);
    float2 f23 = __half22float2(*(__half2*)&hi);
    acc.x += f01.x; acc.y += f01.y; acc.z += f23.x; acc.w += f23.y;
}
__device__ __forceinline__ unsigned h2bits(float a, float b) {
    __half2 h = __floats2half2_rn(a, b);
    return *(unsigned*)&h;
}
__device__ __forceinline__ ull pack_h4u(float a, float b, float c, float d) {
    unsigned u0 = h2bits(a, b), u1 = h2bits(c, d);
    return ((ull)u1 << 32) | u0;
}
__device__ __forceinline__ unsigned smem_u32(const void* p) {
    unsigned a;
    asm("{ .reg .u64 t; cvta.to.shared.u64 t, %1; cvt.u32.u64 %0, t; }"
        : "=r"(a) : "l"(p));
    return a;
}
__device__ __forceinline__ void ldsm_x4(unsigned &r0, unsigned &r1,
                                        unsigned &r2, unsigned &r3, unsigned a) {
    asm volatile("ldmatrix.sync.aligned.m8n8.x4.shared.b16 {%0,%1,%2,%3}, [%4];"
                 : "=r"(r0), "=r"(r1), "=r"(r2), "=r"(r3) : "r"(a));
}
__device__ __forceinline__ void ldsm_x4t(unsigned &r0, unsigned &r1,
                                         unsigned &r2, unsigned &r3, unsigned a) {
    asm volatile("ldmatrix.sync.aligned.m8n8.x4.trans.shared.b16 {%0,%1,%2,%3}, [%4];"
                 : "=r"(r0), "=r"(r1), "=r"(r2), "=r"(r3) : "r"(a));
}
__device__ __forceinline__ void mma_f16(float c[4], unsigned a0, unsigned a1,
                                        unsigned a2, unsigned a3,
                                        unsigned b0, unsigned b1) {
    asm("mma.sync.aligned.m16n8k16.row.col.f32.f16.f16.f32 "
        "{%0,%1,%2,%3}, {%4,%5,%6,%7}, {%8,%9}, {%0,%1,%2,%3};"
        : "+f"(c[0]), "+f"(c[1]), "+f"(c[2]), "+f"(c[3])
        : "r"(a0), "r"(a1), "r"(a2), "r"(a3), "r"(b0), "r"(b1));
}

// ---------------- K0: zero scratch ----------------
__global__ void k_zero() {
    int i = blockIdx.x * blockDim.x + threadIdx.x;
    int st = gridDim.x * blockDim.x;
    float4 z = make_float4(0.f, 0.f, 0.f, 0.f);
    for (int j = i; j < NN * DE / 4; j += st) ((float4*)g_agge)[j] = z;
    for (int j = i; j < NN; j += st) { g_se[j] = 0.f; g_deg[j] = 0; }
    if (i == 0) g_novf = 0;
}

// ---------------- K1: build per-dst src buckets + degree ----------------
__global__ void k_build(const int* __restrict__ src, const int* __restrict__ dst) {
    int e = blockIdx.x * blockDim.x + threadIdx.x;
    if (e >= NE) return;
    int d = dst[e], s = src[e];
    int c = atomicAdd(&g_deg[d], 1);
    if (c < CAP) {
        g_perm[d * CAP + c] = s;
    } else {
        int o = atomicAdd(&g_novf, 1);
        if (o < 2048) g_ovf[o] = make_int2(s, d);
    }
}

// ---------------- K1b: norm = (deg+1)^-1/2 ----------------
__global__ void k_norm() {
    int i = blockIdx.x * blockDim.x + threadIdx.x;
    if (i < NN) g_norm[i] = rsqrtf((float)g_deg[i] + 1.0f);
}

// ---------------- KA: edge-parallel efeat scatter (2 edges per round) ----------------
__global__ __launch_bounds__(256) void k_edge_e(
    const int* __restrict__ src, const int* __restrict__ dst,
    const float* __restrict__ efeat)
{
    int lane = threadIdx.x & 31;
    int warp = (blockIdx.x * blockDim.x + threadIdx.x) >> 5;   // 25000 warps
    int e0   = warp * 32;
    if (e0 >= NE) return;

    int s = src[e0 + lane];
    int d = dst[e0 + lane];
    float ns = ldgf(&g_norm[s]);
    atomicAdd(&g_se[d], ns);

    ull pol;
    asm("createpolicy.fractional.L2::evict_first.b64 %0, 1.0;" : "=l"(pol));

    int half = lane >> 4;
    int l16  = lane & 15;
    const float* ep = &efeat[(size_t)e0 * DE + 4 * l16];

    #pragma unroll
    for (int j = 0; j < 32; j += 2) {
        int idx = j + half;
        int   dj  = __shfl_sync(0xffffffffu, d, idx);
        float nsj = __shfl_sync(0xffffffffu, ns, idx);
        float4 ev = ldg4_ef(ep + (size_t)idx * DE, pol);
        red4(&g_agge[(size_t)dj * DE + 4 * l16],
             make_float4(nsj * ev.x, nsj * ev.y, nsj * ev.z, nsj * ev.w));
    }
}

// ---------------- K2: fp16 HMMA node GEMM, 64x128 tile, 3 blocks/SM ---------------
// h = nfeat@Wn + bn ; g16 = fp16(norm*h) ; out = (h+resid)/deg
// 8 warps as 4x2: wr = w&3 owns rows 16wr..16wr+15; wc = w>>2 owns cols 64wc..64wc+63.
// Accumulators: 8 n8-tiles x 4 = 32 floats/thread.
__global__ __launch_bounds__(256, 3) void k_node_mma(
    const float* __restrict__ nfeat, const float* __restrict__ Wn,
    const float* __restrict__ bn, const float* __restrict__ resid,
    float* __restrict__ out)
{
    extern __shared__ __half smh[];
    __half* sA = smh;              // [64][136] fp16
    __half* sB = smh + 64 * 136;   // [128][136] fp16 (Wn as [k][n])

    int t = threadIdx.x, lane = t & 31, w = t >> 5;
    int wr = w & 3, wc = w >> 2;
    int g = lane >> 2, tig = lane & 3;
    int q = lane >> 3, l8 = lane & 7;

    // stage Wn once as fp16 (16 iters/thread)
    for (int i = t; i < 128 * 32; i += 256) {
        int k  = i >> 5;
        int c4 = (i & 31) * 4;
        float4 v = *(const float4*)&Wn[(size_t)k * 128 + c4];
        *(ull*)&sB[k * 136 + c4] = pack_h4u(v.x, v.y, v.z, v.w);
    }

    unsigned sAu = smem_u32(sA), sBu = smem_u32(sB);
    // A frag: row = 16wr + (q&1)*8 + l8, col = (q>>1)*8 (+k0)
    unsigned addrA0 = sAu + ((unsigned)((16 * wr + (q & 1) * 8 + l8) * 136
                                        + (q >> 1) * 8) << 1);
    // B frag: row = (q&1)*8 + l8 (+k0), col = 64wc + (q>>1)*8 (+16*jp)
    unsigned addrB0 = sBu + ((unsigned)(((q & 1) * 8 + l8) * 136
                                        + 64 * wc + (q >> 1) * 8) << 1);

    const int NT = (NN + 63) / 64;   // 782
    for (int tile = blockIdx.x; tile < NT; tile += gridDim.x) {
        __syncthreads();
        // stage A tile (64 rows) as fp16, zero-pad past NN (8 iters/thread)
        for (int i = t; i < 64 * 32; i += 256) {
            int r  = i >> 5;
            int c4 = (i & 31) * 4;
            int gn = tile * 64 + r;
            float4 v = make_float4(0.f, 0.f, 0.f, 0.f);
            if (gn < NN) v = *(const float4*)&nfeat[(size_t)gn * 128 + c4];
            *(ull*)&sA[r * 136 + c4] = pack_h4u(v.x, v.y, v.z, v.w);
        }
        __syncthreads();

        float c[8][4];
        #pragma unroll
        for (int j = 0; j < 8; j++)
            c[j][0] = c[j][1] = c[j][2] = c[j][3] = 0.f;

        #pragma unroll
        for (int ks = 0; ks < 8; ks++) {
            int k0 = ks * 16;
            unsigned a0, a1, a2, a3;
            ldsm_x4(a0, a1, a2, a3, addrA0 + (k0 << 1));
            #pragma unroll
            for (int jp = 0; jp < 4; jp++) {
                unsigned b0, b1, b2, b3;
                ldsm_x4t(b0, b1, b2, b3,
                         addrB0 + ((unsigned)(k0 * 136 + 16 * jp) << 1));
                mma_f16(c[2 * jp],     a0, a1, a2, a3, b0, b1);
                mma_f16(c[2 * jp + 1], a0, a1, a2, a3, b2, b3);
            }
        }

        // epilogue: rows n0 = base+g, n1 = n0+8; cols 64wc+8j+2tig
        int n0 = tile * 64 + 16 * wr + g;
        int n1 = n0 + 8;
        bool v0 = n0 < NN, v1 = n1 < NN;
        float dv0 = v0 ? (float)g_deg[n0] + 1.0f : 1.0f;
        float dv1 = v1 ? (float)g_deg[n1] + 1.0f : 1.0f;
        float inv0 = 1.0f / dv0, nr0 = rsqrtf(dv0);
        float inv1 = 1.0f / dv1, nr1 = rsqrtf(dv1);

        unsigned* g32 = (unsigned*)g_g16;
        #pragma unroll
        for (int j = 0; j < 8; j++) {
            int col = 64 * wc + 8 * j + 2 * tig;
            float2 bn2 = *(const float2*)&bn[col];
            float2 r2  = *(const float2*)&resid[col];
            float h0 = c[j][0] + bn2.x, h1 = c[j][1] + bn2.y;
            float h2 = c[j][2] + bn2.x, h3 = c[j][3] + bn2.y;
            if (v0) {
                g32[(size_t)n0 * 64 + (col >> 1)] = h2bits(nr0 * h0, nr0 * h1);
                *(float2*)&out[(size_t)n0 * D + col] =
                    make_float2((h0 + r2.x) * inv0, (h1 + r2.y) * inv0);
            }
            if (v1) {
                g32[(size_t)n1 * 64 + (col >> 1)] = h2bits(nr1 * h2, nr1 * h3);
                *(float2*)&out[(size_t)n1 * D + col] =
                    make_float2((h2 + r2.x) * inv1, (h3 + r2.y) * inv1);
            }
        }
    }
}

// ---------------- K3: tiled GEMM  out += norm * (agge@We + se*be)  [red4] ----------
__global__ __launch_bounds__(256) void k_gemm2(
    const float* __restrict__ We, const float* __restrict__ be,
    float* __restrict__ out)
{
    extern __shared__ ull smg[];
    ull*   sWe = smg;                      // [64][64] u64 (We dim-pairs) = 32 KB
    float* sAg = (float*)(smg + 64 * 64);  // [k][node] = 16 KB

    int t = threadIdx.x, lane = t & 31, w = t >> 5;

    const ulonglong2* We128 = (const ulonglong2*)We;
    ulonglong2* sWe2 = (ulonglong2*)sWe;
    for (int i = t; i < 64 * 64 / 2; i += 256) sWe2[i] = We128[i];

    float4 be4 = *(const float4*)&be[4 * lane];

    int nodeL = t & 63;
    int q     = t >> 6;

    const int NT = (NN + 63) / 64;
    for (int tile = blockIdx.x; tile < NT; tile += gridDim.x) {
        __syncthreads();
        int gn = tile * 64 + nodeL;
        #pragma unroll
        for (int i = 0; i < 4; i++) {
            int k0 = 16 * q + 4 * i;
            float4 v = make_float4(0.f, 0.f, 0.f, 0.f);
            if (gn < NN) v = *(const float4*)&g_agge[(size_t)gn * DE + k0];
            sAg[(k0 + 0) * 64 + nodeL] = v.x;
            sAg[(k0 + 1) * 64 + nodeL] = v.y;
            sAg[(k0 + 2) * 64 + nodeL] = v.z;
            sAg[(k0 + 3) * 64 + nodeL] = v.w;
        }
        __syncthreads();

        ull acc[8][2];
        #pragma unroll
        for (int j = 0; j < 8; j++) { acc[j][0] = 0ULL; acc[j][1] = 0ULL; }

        #pragma unroll 8
        for (int k = 0; k < 64; k++) {
            ulonglong2 wv = *(const ulonglong2*)&sWe[k * 64 + 2 * lane];
            float4 f0 = *(const float4*)&sAg[k * 64 + 8 * w];
            float4 f1 = *(const float4*)&sAg[k * 64 + 8 * w + 4];
            float fv[8] = {f0.x, f0.y, f0.z, f0.w, f1.x, f1.y, f1.z, f1.w};
            #pragma unroll
            for (int j = 0; j < 8; j++) {
                ull dj = dup2(fv[j]);
                fma2(acc[j][0], dj, wv.x);
                fma2(acc[j][1], dj, wv.y);
            }
        }

        #pragma unroll
        for (int j = 0; j < 8; j++) {
            int n = tile * 64 + 8 * w + j;
            if (n >= NN) continue;
            float nr = g_norm[n];
            float se = g_se[n];
            float2 p0 = unpk(acc[j][0]), p1 = unpk(acc[j][1]);
            red4(&out[(size_t)n * D + 4 * lane],
                 make_float4(nr * (p0.x + se * be4.x), nr * (p0.y + se * be4.y),
                             nr * (p1.x + se * be4.z), nr * (p1.y + se * be4.w)));
        }
    }
}

// ---------------- K4: node-parallel fp16 g gather (no smem; red4 epilogue) -------------
__global__ __launch_bounds__(256) void k_gath(float* __restrict__ out)
{
    int t = threadIdx.x, lane = t & 31, w = t >> 5;
    int n = blockIdx.x * 8 + w;   // grid = 6250 * 8 warps = 50000
    if (n >= NN) return;

    int deg  = g_deg[n];
    int dcap = deg < CAP ? deg : CAP;
    int base = n * CAP;

    float4 acc = make_float4(0.f, 0.f, 0.f, 0.f);

    for (int c0 = 0; c0 < dcap; c0 += 32) {
        int m = dcap - c0; if (m > 32) m = 32;
        int s_l = 0;
        if (lane < m) s_l = g_perm[base + c0 + lane];

        int i = 0;
        for (; i + 8 <= m; i += 8) {
            int sa[8];
            #pragma unroll
            for (int k = 0; k < 8; k++) sa[k] = __shfl_sync(0xffffffffu, s_l, i + k);
            ull gv[8];
            #pragma unroll
            for (int k = 0; k < 8; k++) gv[k] = ldg1(&g_g16[(size_t)sa[k] * 32 + lane]);
            #pragma unroll
            for (int k = 0; k < 8; k++) acc_h4(acc, gv[k]);
        }
        for (; i < m; i++) {
            int s = __shfl_sync(0xffffffffu, s_l, i);
            ull gv = ldg1(&g_g16[(size_t)s * 32 + lane]);
            acc_h4(acc, gv);
        }
    }

    float nr = g_norm[n];
    red4(&out[(size_t)n * D + 4 * lane],
         make_float4(nr * acc.x, nr * acc.y, nr * acc.z, nr * acc.w));
}

// ---------------- K5: overflow fallback — add missing g contributions ----------------
__global__ void k_ovf(float* __restrict__ out) {
    int cnt = g_novf; if (cnt > 2048) cnt = 2048;
    if (cnt <= 0) return;
    int lane = threadIdx.x & 31;
    int warp = (blockIdx.x * blockDim.x + threadIdx.x) >> 5;
    int nw   = (gridDim.x * blockDim.x) >> 5;
    for (int o = warp; o < cnt; o += nw) {
        int2 v = g_ovf[o];
        int s = v.x, d = v.y;
        float nd = g_norm[d];
        float4 acc = make_float4(0.f, 0.f, 0.f, 0.f);
        acc_h4(acc, g_g16[(size_t)s * 32 + lane]);
        red4(&out[(size_t)d * D + 4 * lane],
             make_float4(nd * acc.x, nd * acc.y, nd * acc.z, nd * acc.w));
    }
}

// ---------------- launch: fork/join two streams inside graph capture ----------------
extern "C" void kernel_launch(void* const* d_in, const int* in_sizes, int n_in,
                              void* d_out, int out_size)
{
    const int*   src   = (const int*)  d_in[0];
    const int*   dst   = (const int*)  d_in[1];
    const float* nfeat = (const float*)d_in[2];
    const float* efeat = (const float*)d_in[3];
    const float* Wn    = (const float*)d_in[4];
    const float* bn    = (const float*)d_in[5];
    const float* We    = (const float*)d_in[6];
    const float* be    = (const float*)d_in[7];
    const float* resid = (const float*)d_in[8];
    float* out = (float*)d_out;

    const int SM_MMA = (64 * 136 + 128 * 136) * 2;   // 52.2 KB (fp16 A + B)
    const int SM_G2  = 64 * 64 * 8 + 64 * 64 * 4;    // 48 KB
    cudaFuncSetAttribute(k_node_mma, cudaFuncAttributeMaxDynamicSharedMemorySize, SM_MMA);
    cudaFuncSetAttribute(k_gemm2,    cudaFuncAttributeMaxDynamicSharedMemorySize, SM_G2);

    cudaStream_t sA;
    cudaStreamCreateWithFlags(&sA, cudaStreamNonBlocking);
    cudaEvent_t eFork, eNode, eEnd;
    cudaEventCreateWithFlags(&eFork, cudaEventDisableTiming);
    cudaEventCreateWithFlags(&eNode, cudaEventDisableTiming);
    cudaEventCreateWithFlags(&eEnd,  cudaEventDisableTiming);

    // serial prologue on the capture stream
    k_zero <<<912, 256>>>();
    k_build<<<(NE + 255) / 256, 256>>>(src, dst);
    k_norm <<<(NN + 255) / 256, 256>>>();

    // fork: side stream joins the capture
    cudaEventRecord(eFork, 0);
    cudaStreamWaitEvent(sA, eFork, 0);

    // sA: tensor-core chain          // s0: memory-bound chain (concurrent)
    k_node_mma<<<444, 256, SM_MMA, sA>>>(nfeat, Wn, bn, resid, out);
    k_edge_e  <<<3125, 256, 0, 0>>>(src, dst, efeat);

    cudaEventRecord(eNode, sA);
    k_gath<<<6250, 256, 0, sA>>>(out);           // needs g_g16 + out base (sA order)
    k_ovf <<<16, 256, 0, sA>>>(out);

    cudaStreamWaitEvent(0, eNode, 0);            // gemm2 needs out base from k_node_mma
    k_gemm2<<<782, 256, SM_G2, 0>>>(We, be, out); // after edge_e (s0 order) + eNode

    // join side stream back into the capture stream
    cudaEventRecord(eEnd, sA);
    cudaStreamWaitEvent(0, eEnd, 0);
}